// round 14
// baseline (speedup 1.0000x reference)
#include <cuda_runtime.h>
#include <cuda_pipeline.h>
#include <math.h>

#define NIMG 4
#define NCLS 19
#define HWPIX 589824            // 768*768
#define NTOT (NIMG * HWPIX)
#define IGN 255
#define EDGE_T 0.8f
#define PPT 4                   // pixels per thread
#define TPB 256
#define BPI (HWPIX / (TPB * PPT))   // 576 blocks per image
#define GRID (NIMG * BPI)           // 2304
#define INVC 31                 // "invalid" sentinel -> absorber slot 31 (19..31 unused in finalize)
#define PDEPTH 6                // cp.async prefetch depth (channels)

// ---------------- device-global scratch (no allocations allowed) ----------------
// Per-image arrays padded to 32 slots so INVC (31) is a harmless absorber.
__device__ float  g_ssum[NIMG * 32];     // per-class nll sums (fp32 RED targets)
__device__ float  g_asum[NIMG * 32];     // per-class att nll sums
__device__ int    g_cnt [NIMG * 32];     // seg cnt lo16 | att cnt hi16
__device__ double g_bce_pos, g_bce_neg;
__device__ int    g_pos, g_neg;
__device__ unsigned g_done;

// ---------------- single fused kernel ----------------
// cp.async SMEM ring (R10, proven) + fire-and-forget global REDs for the
// per-class epilogue: no shuffle storm (R10: 630 issue slots), no shared
// atomics (R11: LSU-bound). Hottest RED address gets ~31k ops over ~80k
// cycles -> under the 1/cyc per-address L2-atomic ceiling, fully absorbed.
__global__ void __launch_bounds__(TPB) k_fused(const float* __restrict__ segin,
                                               const float* __restrict__ edgein,
                                               const int* __restrict__ segmask,
                                               const int* __restrict__ emask,
                                               float* __restrict__ out) {
    __shared__ float4 pbuf[PDEPTH][TPB];     // 24 KB prefetch ring (per-thread slots)

    int n   = blockIdx.x / BPI;
    int tid = threadIdx.x;
    int lid = tid & 31;

    int local = (blockIdx.x % BPI) * (TPB * PPT) + tid * PPT;
    int p     = n * HWPIX + local;

    const float* sp = segin + (size_t)n * (size_t)NCLS * (size_t)HWPIX + (size_t)local;

    // kick off the segin pipeline FIRST so DRAM is busy during the prologue
#pragma unroll
    for (int c = 0; c < PDEPTH; c++) {
        __pipeline_memcpy_async(&pbuf[c][tid], sp + (size_t)c * HWPIX, 16);
        __pipeline_commit();
    }

    // ---- prologue: masks + BCE ----
    int4   t4 = *(const int4*)(segmask + p);
    float4 e4 = *(const float4*)(edgein + p);
    int4   m4 = *(const int4*)(emask + p);

    int   tv[PPT] = {t4.x, t4.y, t4.z, t4.w};
    float ev[PPT] = {e4.x, e4.y, e4.z, e4.w};
    int   mv[PPT] = {m4.x, m4.y, m4.z, m4.w};

    int tcls[PPT];               // class for select; INVC for ignored pixels
    unsigned attb = 0u;
    float bce_p = 0.f, bce_n = 0.f;
    unsigned pn = 0;             // pos lo16, neg hi16 (warp max 128 each: safe)
#pragma unroll
    for (int i = 0; i < PPT; i++) {
        bool v  = (tv[i] != IGN);
        tcls[i] = v ? min(max(tv[i], 0), NCLS - 1) : INVC;
        if (v && (ev[i] > EDGE_T)) attb |= (1u << i);

        float xx = ev[i];
        float b  = fmaxf(xx, 0.f) - xx * (float)mv[i] + log1pf(__expf(-fabsf(xx)));
        if (mv[i] == 1) { bce_p += b; pn += 1u; }
        else if (mv[i] == 0) { bce_n += b; pn += 0x10000u; }
    }

    // ---- channel sweep out of the SMEM ring ----
    float s[PPT], xt[PPT];
#pragma unroll
    for (int i = 0; i < PPT; i++) { s[i] = 0.f; xt[i] = 0.f; }

#pragma unroll
    for (int c = 0; c < NCLS; c++) {
        __pipeline_wait_prior(PDEPTH - 1);        // channel c's copy has landed
        float4 x = pbuf[c % PDEPTH][tid];
        int cn = c + PDEPTH;
        if (cn < NCLS)
            __pipeline_memcpy_async(&pbuf[c % PDEPTH][tid], sp + (size_t)cn * HWPIX, 16);
        __pipeline_commit();                      // keep group numbering uniform

        float xv[PPT] = {x.x, x.y, x.z, x.w};
#pragma unroll
        for (int i = 0; i < PPT; i++) {
            s[i] += __expf(xv[i]);
            xt[i] = (c == tcls[i]) ? xv[i] : xt[i];
        }
    }

    // ---- per-pixel nll -> fire-and-forget global REDs (slot 31 absorbs ignored) ----
#pragma unroll
    for (int i = 0; i < PPT; i++) {
        float nll = __logf(s[i]) - xt[i];        // -log_softmax[target]
        bool  a   = (attb >> i) & 1u;
        int   gi  = (n << 5) + tcls[i];
        atomicAdd(&g_ssum[gi], nll);             // RED.ADD.F32, no return
        if (a) atomicAdd(&g_asum[gi], nll);
        atomicAdd(&g_cnt[gi], a ? 0x10001 : 1);
    }

    // ---- BCE: cheap warp reduce, one RED per warp ----
    for (int o = 16; o; o >>= 1) {
        bce_p += __shfl_down_sync(0xffffffffu, bce_p, o);
        bce_n += __shfl_down_sync(0xffffffffu, bce_n, o);
    }
    pn = __reduce_add_sync(0xffffffffu, pn);
    if (lid == 0) {
        atomicAdd(&g_bce_pos, (double)bce_p);
        atomicAdd(&g_bce_neg, (double)bce_n);
        atomicAdd(&g_pos, (int)(pn & 0xffffu));
        atomicAdd(&g_neg, (int)(pn >> 16));
    }

    // ---- fan-in: last block finalizes ----
    __syncthreads();
    __shared__ unsigned s_last;
    if (tid == 0) {
        __threadfence();
        s_last = (atomicAdd(&g_done, 1u) == GRID - 1u);
    }
    __syncthreads();
    if (!s_last) return;
    __threadfence();   // acquire: make all blocks' RED results visible

    // ---------------- finalize (parallel, division-light) ----------------
    __shared__ double f_ss[NIMG * NCLS], f_as[NIMG * NCLS];
    __shared__ int    f_sc[NIMG * NCLS], f_ac[NIMG * NCLS];
    __shared__ double f_rs[NIMG], f_ra[NIMG];
    __shared__ double f_t[NIMG * NCLS][4];
    __shared__ double f_img[NIMG][2];
    __shared__ double f_bce[2];
    __shared__ int    f_pn[2];

    if (tid < NIMG * NCLS) {
        int ni = tid / NCLS, c = tid - ni * NCLS;
        int gi = (ni << 5) + c;
        f_ss[tid] = (double)g_ssum[gi];
        f_as[tid] = (double)g_asum[gi];
        int cc = g_cnt[gi];
        f_sc[tid] = cc & 0xffff;
        f_ac[tid] = cc >> 16;
    }
    if (tid == 96) { f_bce[0] = g_bce_pos; f_bce[1] = g_bce_neg; }
    if (tid == 97) { f_pn[0] = g_pos; f_pn[1] = g_neg; }
    __syncthreads();

    if (tid < NIMG) {
        int ssum = 0, asum = 0;
#pragma unroll
        for (int c = 0; c < NCLS; c++) { ssum += f_sc[tid * NCLS + c]; asum += f_ac[tid * NCLS + c]; }
        f_rs[tid] = 1.0 / (double)ssum;
        f_ra[tid] = 1.0 / (double)asum;
    }
    __syncthreads();

    if (tid < NIMG * NCLS) {
        int nimg = tid / NCLS;
        int sc = f_sc[tid], ac = f_ac[tid];
        double ws = sc ? (2.0 - (double)sc * f_rs[nimg]) : 1.0;
        double wa = ac ? (2.0 - (double)ac * f_ra[nimg]) : 1.0;
        f_t[tid][0] = ws * f_ss[tid];
        f_t[tid][1] = ws * (double)sc;
        f_t[tid][2] = wa * f_as[tid];
        f_t[tid][3] = wa * (double)ac;
    }
    __syncthreads();

    if (tid < NIMG) {
        double sn = 0, sd = 0, an = 0, ad = 0;
#pragma unroll
        for (int c = 0; c < NCLS; c++) {
            sn += f_t[tid * NCLS + c][0]; sd += f_t[tid * NCLS + c][1];
            an += f_t[tid * NCLS + c][2]; ad += f_t[tid * NCLS + c][3];
        }
        f_img[tid][0] = sn / sd;
        f_img[tid][1] = an / ad;
    }
    __syncthreads();

    if (tid == 0) {
        double segl = 0.0, attl = 0.0;
#pragma unroll
        for (int nn2 = 0; nn2 < NIMG; nn2++) { segl += f_img[nn2][0]; attl += f_img[nn2][1]; }
        double pp = (double)f_pn[0], nng = (double)f_pn[1], sm = pp + nng;
        double bce = ((nng / sm) * f_bce[0] + (pp / sm) * f_bce[1]) / (double)NTOT;
        out[0] = (float)(segl + 0.3 * bce + 0.1 * attl);
    }

    // reset scratch for next graph replay
    if (tid < NIMG * 32) { g_ssum[tid] = 0.f; g_asum[tid] = 0.f; g_cnt[tid] = 0; }
    if (tid == 128) { g_bce_pos = 0.0; g_bce_neg = 0.0; }
    if (tid == 129) { g_pos = 0; g_neg = 0; }
    if (tid == 130) g_done = 0u;
}

extern "C" void kernel_launch(void* const* d_in, const int* in_sizes, int n_in,
                              void* d_out, int out_size) {
    const float* segin   = (const float*)d_in[0];
    const float* edgein  = (const float*)d_in[1];
    const int*   segmask = (const int*)d_in[2];
    const int*   emask   = (const int*)d_in[3];

    k_fused<<<GRID, TPB>>>(segin, edgein, segmask, emask, (float*)d_out);
}

// round 15
// speedup vs baseline: 10.0577x; 10.0577x over previous
#include <cuda_runtime.h>
#include <cuda_pipeline.h>
#include <math.h>

#define NIMG 4
#define NCLS 19
#define HWPIX 589824            // 768*768
#define NTOT (NIMG * HWPIX)
#define IGN 255
#define EDGE_T 0.8f
#define PPT 8                   // pixels per thread = two coalesced 4-px groups
#define TPB 256
#define GRPPIX (TPB * 4)            // 1024 pixels per group
#define BPI (HWPIX / (TPB * PPT))   // 288 blocks per image
#define GRID (NIMG * BPI)           // 1152
#define INVC 31                 // "invalid" class sentinel (never matches 0..18)
#define PDEPTH 5                // cp.async prefetch depth (channels); 40 KB ring

// ---------------- device-global scratch (no allocations allowed) ----------------
__device__ double g_seg_sum[NIMG * NCLS];
__device__ double g_att_sum[NIMG * NCLS];
__device__ int    g_seg_cnt[NIMG * NCLS];
__device__ int    g_att_cnt[NIMG * NCLS];
__device__ double g_bce_pos, g_bce_neg;
__device__ int    g_pos, g_neg;
__device__ unsigned g_done;

// ---------------- single fused kernel ----------------
// R10's proven cp.async ring + shuffle epilogue, at PPT=8: the fixed per-warp
// epilogue cost (19-class selects + shuffles) is amortized over 2x pixels,
// which is affordable only because cp.async keeps the extra pixels in SMEM,
// not registers. All global accesses stay fully coalesced via two 4-px groups.
__global__ void __launch_bounds__(TPB) k_fused(const float* __restrict__ segin,
                                               const float* __restrict__ edgein,
                                               const int* __restrict__ segmask,
                                               const int* __restrict__ emask,
                                               float* __restrict__ out) {
    __shared__ float4 pbuf[PDEPTH][2][TPB];  // 40 KB ring: [depth][group][thread]

    int n   = blockIdx.x / BPI;
    int tid = threadIdx.x;
    int wid = tid >> 5;
    int lid = tid & 31;

    int base   = (blockIdx.x % BPI) * (TPB * PPT);
    int local0 = base + tid * 4;             // group 0 pixels
    int local1 = base + GRPPIX + tid * 4;    // group 1 pixels (+1024)
    int p0     = n * HWPIX + local0;
    int p1     = n * HWPIX + local1;

    const float* sp0 = segin + (size_t)n * (size_t)NCLS * (size_t)HWPIX + (size_t)local0;
    const float* sp1 = sp0 + GRPPIX;

    // kick off the segin pipeline FIRST so DRAM is busy during the prologue
#pragma unroll
    for (int c = 0; c < PDEPTH; c++) {
        __pipeline_memcpy_async(&pbuf[c][0][tid], sp0 + (size_t)c * HWPIX, 16);
        __pipeline_memcpy_async(&pbuf[c][1][tid], sp1 + (size_t)c * HWPIX, 16);
        __pipeline_commit();                 // one group per channel
    }

    // ---- prologue: masks + BCE for both pixel groups ----
    int4   t40 = *(const int4*)(segmask + p0);
    int4   t41 = *(const int4*)(segmask + p1);
    float4 e40 = *(const float4*)(edgein + p0);
    float4 e41 = *(const float4*)(edgein + p1);
    int4   m40 = *(const int4*)(emask + p0);
    int4   m41 = *(const int4*)(emask + p1);

    int   tv[PPT] = {t40.x, t40.y, t40.z, t40.w, t41.x, t41.y, t41.z, t41.w};
    float ev[PPT] = {e40.x, e40.y, e40.z, e40.w, e41.x, e41.y, e41.z, e41.w};
    int   mv[PPT] = {m40.x, m40.y, m40.z, m40.w, m41.x, m41.y, m41.z, m41.w};

    int tcls[PPT];               // class for select; INVC for ignored pixels
    unsigned attb = 0u;
    float bce_p = 0.f, bce_n = 0.f;
    unsigned pn = 0;             // pos lo16, neg hi16 (warp max 256 each: safe)
#pragma unroll
    for (int i = 0; i < PPT; i++) {
        bool v  = (tv[i] != IGN);
        tcls[i] = v ? min(max(tv[i], 0), NCLS - 1) : INVC;
        if (v && (ev[i] > EDGE_T)) attb |= (1u << i);

        float xx = ev[i];
        float b  = fmaxf(xx, 0.f) - xx * (float)mv[i] + log1pf(__expf(-fabsf(xx)));
        if (mv[i] == 1) { bce_p += b; pn += 1u; }
        else if (mv[i] == 0) { bce_n += b; pn += 0x10000u; }
    }
    // tv/ev/mv dead here

    // ---- channel sweep out of the SMEM ring ----
    float s[PPT], xt[PPT];
#pragma unroll
    for (int i = 0; i < PPT; i++) { s[i] = 0.f; xt[i] = 0.f; }

#pragma unroll
    for (int c = 0; c < NCLS; c++) {
        __pipeline_wait_prior(PDEPTH - 1);        // channel c's copies have landed
        float4 x0 = pbuf[c % PDEPTH][0][tid];
        float4 x1 = pbuf[c % PDEPTH][1][tid];
        int cn = c + PDEPTH;
        if (cn < NCLS) {
            __pipeline_memcpy_async(&pbuf[c % PDEPTH][0][tid], sp0 + (size_t)cn * HWPIX, 16);
            __pipeline_memcpy_async(&pbuf[c % PDEPTH][1][tid], sp1 + (size_t)cn * HWPIX, 16);
        }
        __pipeline_commit();                      // keep group numbering uniform

        float xv[PPT] = {x0.x, x0.y, x0.z, x0.w, x1.x, x1.y, x1.z, x1.w};
#pragma unroll
        for (int i = 0; i < PPT; i++) {
            s[i] += __expf(xv[i]);
            xt[i] = (c == tcls[i]) ? xv[i] : xt[i];
        }
    }

    // ---- per-pixel nll ----
    float nll[PPT], nllA[PPT];
    unsigned addC[PPT];
#pragma unroll
    for (int i = 0; i < PPT; i++) {
        nll[i]  = __logf(s[i]) - xt[i];          // -log_softmax[target]
        bool a  = (attb >> i) & 1u;
        nllA[i] = a ? nll[i] : 0.f;
        addC[i] = a ? 0x10001u : 1u;             // att cnt hi16, seg cnt lo16
    }

    // ---- per-class register select + warp/block reduction (R10-proven) ----
    __shared__ float sh_ss[NCLS][8];
    __shared__ float sh_sa[NCLS][8];
    __shared__ unsigned sh_cc[NCLS][8];
    __shared__ float sh_bp[8], sh_bn[8];
    __shared__ unsigned sh_pn[8];

#pragma unroll
    for (int c = 0; c < NCLS; c++) {
        float ss = 0.f, sa = 0.f;
        unsigned cc = 0u;
#pragma unroll
        for (int i = 0; i < PPT; i++) {
            if (tcls[i] == c) { ss += nll[i]; sa += nllA[i]; cc += addC[i]; }
        }
        for (int o = 16; o; o >>= 1) {
            ss += __shfl_down_sync(0xffffffffu, ss, o);
            sa += __shfl_down_sync(0xffffffffu, sa, o);
        }
        cc = __reduce_add_sync(0xffffffffu, cc);
        if (lid == 0) { sh_ss[c][wid] = ss; sh_sa[c][wid] = sa; sh_cc[c][wid] = cc; }
    }
    for (int o = 16; o; o >>= 1) {
        bce_p += __shfl_down_sync(0xffffffffu, bce_p, o);
        bce_n += __shfl_down_sync(0xffffffffu, bce_n, o);
    }
    pn = __reduce_add_sync(0xffffffffu, pn);
    if (lid == 0) { sh_bp[wid] = bce_p; sh_bn[wid] = bce_n; sh_pn[wid] = pn; }
    __syncthreads();

    if (tid < NCLS) {
        float ss = 0.f, sa = 0.f; unsigned cc = 0u;
#pragma unroll
        for (int w = 0; w < 8; w++) { ss += sh_ss[tid][w]; sa += sh_sa[tid][w]; cc += sh_cc[tid][w]; }
        int gi = n * NCLS + tid;
        atomicAdd(&g_seg_sum[gi], (double)ss);
        atomicAdd(&g_att_sum[gi], (double)sa);
        atomicAdd(&g_seg_cnt[gi], (int)(cc & 0xffffu));
        atomicAdd(&g_att_cnt[gi], (int)(cc >> 16));
    } else if (tid == 32) {
        float bp = 0.f, bn = 0.f; unsigned c = 0u;
#pragma unroll
        for (int w = 0; w < 8; w++) { bp += sh_bp[w]; bn += sh_bn[w]; c += sh_pn[w]; }
        atomicAdd(&g_bce_pos, (double)bp);
        atomicAdd(&g_bce_neg, (double)bn);
        atomicAdd(&g_pos, (int)(c & 0xffffu));
        atomicAdd(&g_neg, (int)(c >> 16));
    }

    // ---- fan-in: last block finalizes ----
    __syncthreads();
    __shared__ unsigned s_last;
    if (tid == 0) {
        __threadfence();
        s_last = (atomicAdd(&g_done, 1u) == GRID - 1u);
    }
    __syncthreads();
    if (!s_last) return;
    __threadfence();   // acquire: make all blocks' g_* writes visible

    // ---------------- finalize (parallel, division-light; R10-proven) ----------------
    __shared__ double f_ss[NIMG * NCLS], f_as[NIMG * NCLS];
    __shared__ int    f_sc[NIMG * NCLS], f_ac[NIMG * NCLS];
    __shared__ double f_rs[NIMG], f_ra[NIMG];
    __shared__ double f_t[NIMG * NCLS][4];
    __shared__ double f_img[NIMG][2];
    __shared__ double f_bce[2];
    __shared__ int    f_pn[2];

    if (tid < NIMG * NCLS) {
        f_ss[tid] = g_seg_sum[tid];
        f_as[tid] = g_att_sum[tid];
        f_sc[tid] = g_seg_cnt[tid];
        f_ac[tid] = g_att_cnt[tid];
    }
    if (tid == 96) { f_bce[0] = g_bce_pos; f_bce[1] = g_bce_neg; }
    if (tid == 97) { f_pn[0] = g_pos; f_pn[1] = g_neg; }
    __syncthreads();

    if (tid < NIMG) {
        int ssum = 0, asum = 0;
#pragma unroll
        for (int c = 0; c < NCLS; c++) { ssum += f_sc[tid * NCLS + c]; asum += f_ac[tid * NCLS + c]; }
        f_rs[tid] = 1.0 / (double)ssum;
        f_ra[tid] = 1.0 / (double)asum;
    }
    __syncthreads();

    if (tid < NIMG * NCLS) {
        int nimg = tid / NCLS;
        int sc = f_sc[tid], ac = f_ac[tid];
        double ws = sc ? (2.0 - (double)sc * f_rs[nimg]) : 1.0;
        double wa = ac ? (2.0 - (double)ac * f_ra[nimg]) : 1.0;
        f_t[tid][0] = ws * f_ss[tid];
        f_t[tid][1] = ws * (double)sc;
        f_t[tid][2] = wa * f_as[tid];
        f_t[tid][3] = wa * (double)ac;
    }
    __syncthreads();

    if (tid < NIMG) {
        double sn = 0, sd = 0, an = 0, ad = 0;
#pragma unroll
        for (int c = 0; c < NCLS; c++) {
            sn += f_t[tid * NCLS + c][0]; sd += f_t[tid * NCLS + c][1];
            an += f_t[tid * NCLS + c][2]; ad += f_t[tid * NCLS + c][3];
        }
        f_img[tid][0] = sn / sd;
        f_img[tid][1] = an / ad;
    }
    __syncthreads();

    if (tid == 0) {
        double segl = 0.0, attl = 0.0;
#pragma unroll
        for (int nn2 = 0; nn2 < NIMG; nn2++) { segl += f_img[nn2][0]; attl += f_img[nn2][1]; }
        double pp = (double)f_pn[0], nng = (double)f_pn[1], sm = pp + nng;
        double bce = ((nng / sm) * f_bce[0] + (pp / sm) * f_bce[1]) / (double)NTOT;
        out[0] = (float)(segl + 0.3 * bce + 0.1 * attl);
    }

    // reset scratch for next graph replay
    if (tid < NIMG * NCLS) {
        g_seg_sum[tid] = 0.0; g_att_sum[tid] = 0.0;
        g_seg_cnt[tid] = 0;   g_att_cnt[tid] = 0;
    }
    if (tid == 96) { g_bce_pos = 0.0; g_bce_neg = 0.0; }
    if (tid == 97) { g_pos = 0; g_neg = 0; }
    if (tid == 98) g_done = 0u;
}

extern "C" void kernel_launch(void* const* d_in, const int* in_sizes, int n_in,
                              void* d_out, int out_size) {
    const float* segin   = (const float*)d_in[0];
    const float* edgein  = (const float*)d_in[1];
    const int*   segmask = (const int*)d_in[2];
    const int*   emask   = (const int*)d_in[3];

    k_fused<<<GRID, TPB>>>(segin, edgein, segmask, emask, (float*)d_out);
}